// round 9
// baseline (speedup 1.0000x reference)
#include <cuda_runtime.h>
#include <stdint.h>

// RT-DETR post-processing, GB300 sm_103a.
// d_in[0]: pred_logits  float32 [256, 1000, 80]
// d_in[1]: pred_boxes   float32 [256, 1000, 4]   (cx, cy, w, h)
// d_in[2]: target_sizes float32 [256, 2]         (img_h, img_w)
// Output float32 concat: [scores 256*300 | labels 256*300 | boxes 256*300*4]

#define NB   256
#define NQ   1000
#define TOPK 300
#define CHUNK 256
#define NCHUNK 4
typedef unsigned long long ull;

__device__ ull g_keys[NB * NQ];
__device__ ull g_sorted[NB * NCHUNK * CHUNK];

// ---------------------------------------------------------------------------
// Kernel 1: 8 queries per warp. 5 coalesced LDG.128 STAGED IN REGISTERS
// (front-batched -> MLP=5 per thread), then smem transpose, group-of-4-lanes
// per query. Exact (max value, min class) via packed 64-bit reduction.
// ---------------------------------------------------------------------------
__global__ void __launch_bounds__(256) score_kernel(const float* __restrict__ logits) {
    __shared__ float4 sh[8][160];          // 8 warps x 8 queries x 20 f4
    int wid  = threadIdx.x >> 5;
    int lane = threadIdx.x & 31;
    int b    = blockIdx.y;
    int q0   = blockIdx.x * 64 + wid * 8;
    if (q0 >= NQ) return;                  // tail warps of last block

    const float4* p = (const float4*)logits + ((size_t)b * NQ + q0) * 20 + lane;
    // Front-batched loads (keep in registers so all 5 LDGs are in flight).
    float4 a0 = p[0], a1 = p[32], a2 = p[64], a3 = p[96], a4 = p[128];
    sh[wid][lane      ] = a0;
    sh[wid][lane +  32] = a1;
    sh[wid][lane +  64] = a2;
    sh[wid][lane +  96] = a3;
    sh[wid][lane + 128] = a4;
    __syncwarp();

    int g = lane >> 2, j = lane & 3;
    const float4* q = &sh[wid][g * 20 + j];
    float4 w0 = q[0], w1 = q[4], w2 = q[8], w3 = q[12], w4 = q[16];

    // Per-lane max of 20 floats.
    float m = fmaxf(fmaxf(fmaxf(fmaxf(fmaxf(w0.x, w0.y), fmaxf(w0.z, w0.w)),
                                fmaxf(fmaxf(w1.x, w1.y), fmaxf(w1.z, w1.w))),
                          fmaxf(fmaxf(fmaxf(w2.x, w2.y), fmaxf(w2.z, w2.w)),
                                fmaxf(fmaxf(w3.x, w3.y), fmaxf(w3.z, w3.w)))),
                    fmaxf(fmaxf(w4.x, w4.y), fmaxf(w4.z, w4.w)));

    // Per-lane lowest class among maxima (reverse-overwrite scan).
    // class of element e of chunk i = 4*j + 16*i + e.
    int cls = 0;
    {
        int cb = 4 * j;
        if (w4.w == m) cls = cb + 64 + 3;
        if (w4.z == m) cls = cb + 64 + 2;
        if (w4.y == m) cls = cb + 64 + 1;
        if (w4.x == m) cls = cb + 64;
        if (w3.w == m) cls = cb + 48 + 3;
        if (w3.z == m) cls = cb + 48 + 2;
        if (w3.y == m) cls = cb + 48 + 1;
        if (w3.x == m) cls = cb + 48;
        if (w2.w == m) cls = cb + 32 + 3;
        if (w2.z == m) cls = cb + 32 + 2;
        if (w2.y == m) cls = cb + 32 + 1;
        if (w2.x == m) cls = cb + 32;
        if (w1.w == m) cls = cb + 16 + 3;
        if (w1.z == m) cls = cb + 16 + 2;
        if (w1.y == m) cls = cb + 16 + 1;
        if (w1.x == m) cls = cb + 16;
        if (w0.w == m) cls = cb + 3;
        if (w0.z == m) cls = cb + 2;
        if (w0.y == m) cls = cb + 1;
        if (w0.x == m) cls = cb;
    }

    // Order-preserving transform + exact (max value, min class) reduction.
    unsigned t  = __float_as_uint(m);
    unsigned u0 = t ^ ((unsigned)((int)t >> 31) | 0x80000000u);
    ull pk = ((ull)u0 << 7) | (unsigned)(127 - cls);
    { ull o = __shfl_xor_sync(0xffffffffu, pk, 1); pk = pk > o ? pk : o; }
    { ull o = __shfl_xor_sync(0xffffffffu, pk, 2); pk = pk > o ? pk : o; }

    if (j == 0) {                          // lanes 0,4,..,28 -> coalesced STG.64
        int qq = q0 + g;
        g_keys[b * NQ + qq] = ((ull)(pk >> 7) << 32)
                            | ((unsigned)(1023 - qq) << 8)
                            | (unsigned)(127 - (int)(pk & 0x7f));
    }
}

// ---------------------------------------------------------------------------
// Bitonic helpers (descending).
// ---------------------------------------------------------------------------
__device__ __forceinline__ void shfl_merge(ull& v, unsigned i, unsigned k) {
    #pragma unroll
    for (int j = 16; j >= 1; j >>= 1) {
        ull pv = __shfl_xor_sync(0xffffffffu, v, j);
        bool keep_max = (((i & k) == 0) == ((i & (unsigned)j) == 0));
        v = keep_max ? (v > pv ? v : pv) : (v < pv ? v : pv);
    }
}
__device__ __forceinline__ void shfl_sort32(ull& v, unsigned i) {
    #pragma unroll
    for (unsigned k = 2; k <= 32; k <<= 1) {
        #pragma unroll
        for (int j = 16; j >= 1; j >>= 1) {
            if ((unsigned)j < k) {
                ull pv = __shfl_xor_sync(0xffffffffu, v, j);
                bool keep_max = (((i & k) == 0) == ((i & (unsigned)j) == 0));
                v = keep_max ? (v > pv ? v : pv) : (v < pv ? v : pv);
            }
        }
    }
}

// ---------------------------------------------------------------------------
// Kernel 2: sort one 256-key chunk descending. grid = NB*4, block = 128.
// ---------------------------------------------------------------------------
__global__ void __launch_bounds__(128) chunk_sort_kernel() {
    __shared__ ull s[CHUNK];
    int b   = blockIdx.x >> 2;
    int c   = blockIdx.x & 3;
    int tid = threadIdx.x;

    int base  = b * NQ + c * CHUNK;
    int nreal = (c == 3) ? (NQ - 3 * CHUNK) : CHUNK;     // 232 or 256

    unsigned i0 = (unsigned)tid, i1 = (unsigned)tid + 128;
    ull v0 = ((int)i0 < nreal) ? g_keys[base + i0] : 0ull;
    ull v1 = ((int)i1 < nreal) ? g_keys[base + i1] : 0ull;

    shfl_sort32(v0, i0);
    shfl_sort32(v1, i1);
    s[i0] = v0; s[i1] = v1;
    __syncthreads();

    #pragma unroll
    for (unsigned k = 64; k <= CHUNK; k <<= 1) {
        for (unsigned j = k >> 1; j >= 32; j >>= 1) {
            #pragma unroll
            for (int half = 0; half < 2; half++) {
                unsigned idx = (unsigned)tid + half * 128;
                unsigned ixj = idx ^ j;
                if (ixj > idx) {
                    ull a = s[idx], cc = s[ixj];
                    bool doswap = ((idx & k) == 0) ? (a < cc) : (a > cc);
                    if (doswap) { s[idx] = cc; s[ixj] = a; }
                }
            }
            __syncthreads();
        }
        v0 = s[i0]; v1 = s[i1];
        shfl_merge(v0, i0, k);
        shfl_merge(v1, i1, k);
        s[i0] = v0; s[i1] = v1;
        __syncthreads();
    }

    int obase = (b * NCHUNK + c) * CHUNK;
    g_sorted[obase + i0] = s[i0];
    g_sorted[obase + i1] = s[i1];
}

// ---------------------------------------------------------------------------
// Merge-path rank select (descending; keys globally unique via query id).
// ---------------------------------------------------------------------------
__device__ __forceinline__ ull
rank_select(const ull* __restrict__ A, const ull* __restrict__ B,
            int r, int NA, int NBL) {
    int lo = r + 1 - NBL; if (lo < 0) lo = 0;
    int hi = r + 1;       if (hi > NA) hi = NA;
    while (lo < hi) {
        int i = (lo + hi) >> 1;
        if (B[r - i] > A[i]) hi = i; else lo = i + 1;
    }
    int is = lo, js = r + 1 - lo;
    ull ka = is ? A[is - 1] : 0xFFFFFFFFFFFFFFFFull;
    ull kb = js ? B[js - 1] : 0xFFFFFFFFFFFFFFFFull;
    return ka < kb ? ka : kb;
}

// ---------------------------------------------------------------------------
// Kernel 3: two-phase merge of 4 sorted 256-lists -> top-300 + epilogue.
// grid = NB, block = 512.
// ---------------------------------------------------------------------------
__global__ void __launch_bounds__(512) merge_kernel(const float* __restrict__ boxes,
                                                    const float* __restrict__ tsz,
                                                    float* __restrict__ out) {
    __shared__ ull L[NCHUNK * CHUNK];
    __shared__ ull M[2][TOPK];
    int b   = blockIdx.x;
    int tid = threadIdx.x;

    L[tid]       = g_sorted[b * NCHUNK * CHUNK + tid];
    L[tid + 512] = g_sorted[b * NCHUNK * CHUNK + tid + 512];
    __syncthreads();

    // Phase 1: top-300 of (chunk0 U chunk1) and (chunk2 U chunk3).
    for (int t = tid; t < 2 * TOPK; t += 512) {
        int pair = t / TOPK;
        int r    = t - pair * TOPK;
        const ull* A = L + pair * 2 * CHUNK;
        M[pair][r] = rank_select(A, A + CHUNK, r, CHUNK, CHUNK);
    }
    __syncthreads();

    // Phase 2: rank tid of M[0] U M[1], then epilogue.
    if (tid < TOPK) {
        ull key = rank_select(M[0], M[1], tid, TOPK, TOPK);

        unsigned u = (unsigned)(key >> 32);
        float logit = (u & 0x80000000u) ? __uint_as_float(u ^ 0x80000000u)
                                        : __uint_as_float(~u);
        float score = 1.0f / (1.0f + expf(-logit));
        bool  valid = (score > 0.05f);

        unsigned lw = (unsigned)(key & 0xffffffffu);
        int qi    = 1023 - (int)((lw >> 8) & 0x3ffu);
        int label = (int)(lw & 0xffu);

        float4 bx = ((const float4*)boxes)[b * NQ + qi];
        float img_h = tsz[b * 2 + 0];
        float img_w = tsz[b * 2 + 1];
        float x0 = (bx.x - 0.5f * bx.z) * img_w;
        float y0 = (bx.y - 0.5f * bx.w) * img_h;
        float x1 = (bx.x + 0.5f * bx.z) * img_w;
        float y1 = (bx.y + 0.5f * bx.w) * img_h;

        float* out_scores = out;
        float* out_labels = out + NB * TOPK;
        float* out_boxes  = out + 2 * NB * TOPK;

        out_scores[b * TOPK + tid] = valid ? score : 0.0f;
        out_labels[b * TOPK + tid] = valid ? (float)label : -1.0f;
        float4 ob = valid ? make_float4(x0, y0, x1, y1)
                          : make_float4(0.f, 0.f, 0.f, 0.f);
        ((float4*)out_boxes)[b * TOPK + tid] = ob;
    }
}

// ---------------------------------------------------------------------------
extern "C" void kernel_launch(void* const* d_in, const int* in_sizes, int n_in,
                              void* d_out, int out_size) {
    const float* logits = (const float*)d_in[0];
    const float* boxes  = (const float*)d_in[1];
    const float* tsz    = (const float*)d_in[2];
    float* out = (float*)d_out;

    dim3 sgrid(16, NB);                    // 16 blocks x 64 queries per row
    score_kernel<<<sgrid, 256>>>(logits);
    chunk_sort_kernel<<<NB * NCHUNK, 128>>>();
    merge_kernel<<<NB, 512>>>(boxes, tsz, out);
}

// round 10
// speedup vs baseline: 1.0880x; 1.0880x over previous
#include <cuda_runtime.h>
#include <stdint.h>

// RT-DETR post-processing, GB300 sm_103a.
// d_in[0]: pred_logits  float32 [256, 1000, 80]
// d_in[1]: pred_boxes   float32 [256, 1000, 4]   (cx, cy, w, h)
// d_in[2]: target_sizes float32 [256, 2]         (img_h, img_w)
// Output float32 concat: [scores 256*300 | labels 256*300 | boxes 256*300*4]

#define NB   256
#define NQ   1000
#define TOPK 300
typedef unsigned long long ull;

__device__ ull g_keys[NB * NQ];

// ---------------------------------------------------------------------------
// Kernel 1: 8 queries per warp. 5 coalesced LDG.128 staged in registers,
// smem transpose, group-of-4-lanes per query. Exact (max value, min class)
// via packed 64-bit reduction. 2 launches total in the pipeline.
// ---------------------------------------------------------------------------
__global__ void __launch_bounds__(256) score_kernel(const float* __restrict__ logits) {
    __shared__ float4 sh[8][160];          // 8 warps x 8 queries x 20 f4
    int wid  = threadIdx.x >> 5;
    int lane = threadIdx.x & 31;
    int b    = blockIdx.y;
    int q0   = blockIdx.x * 64 + wid * 8;
    if (q0 >= NQ) return;                  // tail warps of last block

    const float4* p = (const float4*)logits + ((size_t)b * NQ + q0) * 20 + lane;
    float4 a0 = p[0], a1 = p[32], a2 = p[64], a3 = p[96], a4 = p[128];
    sh[wid][lane      ] = a0;
    sh[wid][lane +  32] = a1;
    sh[wid][lane +  64] = a2;
    sh[wid][lane +  96] = a3;
    sh[wid][lane + 128] = a4;
    __syncwarp();

    int g = lane >> 2, j = lane & 3;
    const float4* q = &sh[wid][g * 20 + j];
    float4 w0 = q[0], w1 = q[4], w2 = q[8], w3 = q[12], w4 = q[16];

    float m = fmaxf(fmaxf(fmaxf(fmaxf(fmaxf(w0.x, w0.y), fmaxf(w0.z, w0.w)),
                                fmaxf(fmaxf(w1.x, w1.y), fmaxf(w1.z, w1.w))),
                          fmaxf(fmaxf(fmaxf(w2.x, w2.y), fmaxf(w2.z, w2.w)),
                                fmaxf(fmaxf(w3.x, w3.y), fmaxf(w3.z, w3.w)))),
                    fmaxf(fmaxf(w4.x, w4.y), fmaxf(w4.z, w4.w)));

    // Per-lane lowest class among maxima (reverse-overwrite scan).
    // class of element e of chunk i = 4*j + 16*i + e.
    int cls = 0;
    {
        int cb = 4 * j;
        if (w4.w == m) cls = cb + 64 + 3;
        if (w4.z == m) cls = cb + 64 + 2;
        if (w4.y == m) cls = cb + 64 + 1;
        if (w4.x == m) cls = cb + 64;
        if (w3.w == m) cls = cb + 48 + 3;
        if (w3.z == m) cls = cb + 48 + 2;
        if (w3.y == m) cls = cb + 48 + 1;
        if (w3.x == m) cls = cb + 48;
        if (w2.w == m) cls = cb + 32 + 3;
        if (w2.z == m) cls = cb + 32 + 2;
        if (w2.y == m) cls = cb + 32 + 1;
        if (w2.x == m) cls = cb + 32;
        if (w1.w == m) cls = cb + 16 + 3;
        if (w1.z == m) cls = cb + 16 + 2;
        if (w1.y == m) cls = cb + 16 + 1;
        if (w1.x == m) cls = cb + 16;
        if (w0.w == m) cls = cb + 3;
        if (w0.z == m) cls = cb + 2;
        if (w0.y == m) cls = cb + 1;
        if (w0.x == m) cls = cb;
    }

    unsigned t  = __float_as_uint(m);
    unsigned u0 = t ^ ((unsigned)((int)t >> 31) | 0x80000000u);
    ull pk = ((ull)u0 << 7) | (unsigned)(127 - cls);
    { ull o = __shfl_xor_sync(0xffffffffu, pk, 1); pk = pk > o ? pk : o; }
    { ull o = __shfl_xor_sync(0xffffffffu, pk, 2); pk = pk > o ? pk : o; }

    if (j == 0) {                          // lanes 0,4,..,28 -> coalesced STG.64
        int qq = q0 + g;
        g_keys[b * NQ + qq] = ((ull)(pk >> 7) << 32)
                            | ((unsigned)(1023 - qq) << 8)
                            | (unsigned)(127 - (int)(pk & 0x7f));
    }
}

// ---------------------------------------------------------------------------
// Bitonic helpers (descending over index space).
// ---------------------------------------------------------------------------
__device__ __forceinline__ void shfl_merge(ull& v, unsigned i, unsigned k) {
    #pragma unroll
    for (int j = 16; j >= 1; j >>= 1) {
        ull pv = __shfl_xor_sync(0xffffffffu, v, j);
        bool keep_max = (((i & k) == 0) == ((i & (unsigned)j) == 0));
        v = keep_max ? (v > pv ? v : pv) : (v < pv ? v : pv);
    }
}
__device__ __forceinline__ void shfl_sort32(ull& v, unsigned i) {
    #pragma unroll
    for (unsigned k = 2; k <= 32; k <<= 1) {
        #pragma unroll
        for (int j = 16; j >= 1; j >>= 1) {
            if ((unsigned)j < k) {
                ull pv = __shfl_xor_sync(0xffffffffu, v, j);
                bool keep_max = (((i & k) == 0) == ((i & (unsigned)j) == 0));
                v = keep_max ? (v > pv ? v : pv) : (v < pv ? v : pv);
            }
        }
    }
}

// ---------------------------------------------------------------------------
// Merge-path rank select (descending; keys unique via embedded query id).
// ---------------------------------------------------------------------------
__device__ __forceinline__ ull
rank_select(const ull* __restrict__ A, const ull* __restrict__ B,
            int r, int NA, int NBL) {
    int lo = r + 1 - NBL; if (lo < 0) lo = 0;
    int hi = r + 1;       if (hi > NA) hi = NA;
    while (lo < hi) {
        int i = (lo + hi) >> 1;
        if (B[r - i] > A[i]) hi = i; else lo = i + 1;
    }
    int is = lo, js = r + 1 - lo;
    ull ka = is ? A[is - 1] : 0xFFFFFFFFFFFFFFFFull;
    ull kb = js ? B[js - 1] : 0xFFFFFFFFFFFFFFFFull;
    return ka < kb ? ka : kb;
}

// ---------------------------------------------------------------------------
// Kernel 2 (fused): one block (512 thr) per row. 16 per-warp register bitonic
// 64-sorts (zero barriers, all warps parallel), then 4-level merge-path tree
// (5 barriers), then epilogue. Critical path ~6 barrier rounds.
// ---------------------------------------------------------------------------
__global__ void __launch_bounds__(512) topk_kernel(const float* __restrict__ boxes,
                                                   const float* __restrict__ tsz,
                                                   float* __restrict__ out) {
    __shared__ ull BUF0[1024];
    __shared__ ull BUF1[1024];
    int b    = blockIdx.x;
    int tid  = threadIdx.x;
    int wid  = tid >> 5;
    int lane = tid & 31;

    // Per-warp 64-sort: warp w owns keys [w*64, w*64+64) of the padded row.
    {
        int e0 = wid * 64 + lane, e1 = e0 + 32;
        ull v0 = (e0 < NQ) ? g_keys[b * NQ + e0] : 0ull;
        ull v1 = (e1 < NQ) ? g_keys[b * NQ + e1] : 0ull;
        unsigned i0 = (unsigned)lane, i1 = (unsigned)lane + 32;
        shfl_sort32(v0, i0);
        shfl_sort32(v1, i1);
        { ull mx = v0 > v1 ? v0 : v1; v1 = v0 > v1 ? v1 : v0; v0 = mx; } // k=64, j=32
        shfl_merge(v0, i0, 64);
        shfl_merge(v1, i1, 64);
        BUF0[wid * 64 + lane]      = v0;
        BUF0[wid * 64 + lane + 32] = v1;
    }
    __syncthreads();

    // L1: 8 merges (64,64) -> BUF1
    #pragma unroll
    for (int t = tid; t < 1024; t += 512) {
        int pair = t >> 7, r = t & 127;
        const ull* A = BUF0 + pair * 128;
        BUF1[t] = rank_select(A, A + 64, r, 64, 64);
    }
    __syncthreads();

    // L2: 4 merges (128,128) -> BUF0
    #pragma unroll
    for (int t = tid; t < 1024; t += 512) {
        int pair = t >> 8, r = t & 255;
        const ull* A = BUF1 + pair * 256;
        BUF0[t] = rank_select(A, A + 128, r, 128, 128);
    }
    __syncthreads();

    // L3: 2 merges (256,256) -> top 300 each -> BUF1
    for (int t = tid; t < 2 * TOPK; t += 512) {
        int pair = t / TOPK, r = t - pair * TOPK;
        const ull* A = BUF0 + pair * 512;
        BUF1[pair * TOPK + r] = rank_select(A, A + 256, r, 256, 256);
    }
    __syncthreads();

    // L4: final (300,300) -> rank tid, then epilogue.
    if (tid < TOPK) {
        ull key = rank_select(BUF1, BUF1 + TOPK, tid, TOPK, TOPK);

        unsigned u = (unsigned)(key >> 32);
        float logit = (u & 0x80000000u) ? __uint_as_float(u ^ 0x80000000u)
                                        : __uint_as_float(~u);
        float score = 1.0f / (1.0f + expf(-logit));
        bool  valid = (score > 0.05f);

        unsigned lw = (unsigned)(key & 0xffffffffu);
        int qi    = 1023 - (int)((lw >> 8) & 0x3ffu);
        int label = (int)(lw & 0xffu);

        float4 bx = ((const float4*)boxes)[b * NQ + qi];
        float img_h = tsz[b * 2 + 0];
        float img_w = tsz[b * 2 + 1];
        float x0 = (bx.x - 0.5f * bx.z) * img_w;
        float y0 = (bx.y - 0.5f * bx.w) * img_h;
        float x1 = (bx.x + 0.5f * bx.z) * img_w;
        float y1 = (bx.y + 0.5f * bx.w) * img_h;

        float* out_scores = out;
        float* out_labels = out + NB * TOPK;
        float* out_boxes  = out + 2 * NB * TOPK;

        out_scores[b * TOPK + tid] = valid ? score : 0.0f;
        out_labels[b * TOPK + tid] = valid ? (float)label : -1.0f;
        float4 ob = valid ? make_float4(x0, y0, x1, y1)
                          : make_float4(0.f, 0.f, 0.f, 0.f);
        ((float4*)out_boxes)[b * TOPK + tid] = ob;
    }
}

// ---------------------------------------------------------------------------
extern "C" void kernel_launch(void* const* d_in, const int* in_sizes, int n_in,
                              void* d_out, int out_size) {
    const float* logits = (const float*)d_in[0];
    const float* boxes  = (const float*)d_in[1];
    const float* tsz    = (const float*)d_in[2];
    float* out = (float*)d_out;

    dim3 sgrid(16, NB);                    // 16 blocks x 64 queries per row
    score_kernel<<<sgrid, 256>>>(logits);
    topk_kernel<<<NB, 512>>>(boxes, tsz, out);
}